// round 1
// baseline (speedup 1.0000x reference)
#include <cuda_runtime.h>
#include <math.h>

// ---------------- problem constants ----------------
#define BATCH 2
#define HH 256
#define WW_ 256
#define CC 180
#define C5 36
#define NHD 6
#define HD 15
#define L 256
#define ML 64
#define NWIN 512            // total windows (2 * 16 * 16)
#define PTOT (BATCH*HH*WW_) // 131072 pixels

// ---------------- device scratch (static, allowed) ----------------
__device__ float s_y1[PTOT * C5];
__device__ float s_y2[PTOT * C5];
__device__ float s_qv[PTOT * CC];
__device__ float s_cat[PTOT * CC];
__device__ float s_vp[NWIN * NHD * ML * HD];
__device__ float s_rpb[NHD * L * ML];
__device__ float s_tab[961 * NHD];

// ================= position-bias MLP table (961 x 6) =================
__global__ void k_postab(const float* __restrict__ pw, const float* __restrict__ pb,
                         const float* __restrict__ g1, const float* __restrict__ b1,
                         const float* __restrict__ m1w, const float* __restrict__ m1b,
                         const float* __restrict__ g2, const float* __restrict__ b2,
                         const float* __restrict__ m2w, const float* __restrict__ m2b,
                         const float* __restrict__ g3, const float* __restrict__ b3,
                         const float* __restrict__ m3w, const float* __restrict__ m3b) {
    int t = blockIdx.x * blockDim.x + threadIdx.x;
    if (t >= 961) return;
    int a = t / 31, bcol = t - a * 31;
    float gx = (float)a - 15.f, gy = (float)bcol - 15.f;
    float p[11], q[11];
#pragma unroll
    for (int j = 0; j < 11; j++) p[j] = gx * pw[j] + gy * pw[11 + j] + pb[j];

    // layer 1: LN -> relu -> mlp1
    {
        float m = 0.f;
#pragma unroll
        for (int j = 0; j < 11; j++) m += p[j];
        m *= (1.f / 11.f);
        float v = 0.f;
#pragma unroll
        for (int j = 0; j < 11; j++) { float d = p[j] - m; v += d * d; }
        v *= (1.f / 11.f);
        float inv = 1.f / sqrtf(v + 1e-5f);
#pragma unroll
        for (int j = 0; j < 11; j++) {
            float h = (p[j] - m) * inv * g1[j] + b1[j];
            q[j] = h > 0.f ? h : 0.f;
        }
#pragma unroll
        for (int j = 0; j < 11; j++) {
            float acc = m1b[j];
#pragma unroll
            for (int k = 0; k < 11; k++) acc += q[k] * m1w[k * 11 + j];
            p[j] = acc;
        }
    }
    // layer 2
    {
        float m = 0.f;
#pragma unroll
        for (int j = 0; j < 11; j++) m += p[j];
        m *= (1.f / 11.f);
        float v = 0.f;
#pragma unroll
        for (int j = 0; j < 11; j++) { float d = p[j] - m; v += d * d; }
        v *= (1.f / 11.f);
        float inv = 1.f / sqrtf(v + 1e-5f);
#pragma unroll
        for (int j = 0; j < 11; j++) {
            float h = (p[j] - m) * inv * g2[j] + b2[j];
            q[j] = h > 0.f ? h : 0.f;
        }
#pragma unroll
        for (int j = 0; j < 11; j++) {
            float acc = m2b[j];
#pragma unroll
            for (int k = 0; k < 11; k++) acc += q[k] * m2w[k * 11 + j];
            p[j] = acc;
        }
    }
    // layer 3: LN -> relu -> mlp3 (11 -> 6)
    {
        float m = 0.f;
#pragma unroll
        for (int j = 0; j < 11; j++) m += p[j];
        m *= (1.f / 11.f);
        float v = 0.f;
#pragma unroll
        for (int j = 0; j < 11; j++) { float d = p[j] - m; v += d * d; }
        v *= (1.f / 11.f);
        float inv = 1.f / sqrtf(v + 1e-5f);
#pragma unroll
        for (int j = 0; j < 11; j++) {
            float h = (p[j] - m) * inv * g3[j] + b3[j];
            q[j] = h > 0.f ? h : 0.f;
        }
#pragma unroll
        for (int n = 0; n < 6; n++) {
            float acc = m3b[n];
#pragma unroll
            for (int k = 0; k < 11; k++) acc += q[k] * m3w[k * 6 + n];
            s_tab[t * 6 + n] = acc;
        }
    }
}

// ================= rpb gather/average: (6, 256, 64) =================
__global__ void k_rpb() {
    int u = blockIdx.x * blockDim.x + threadIdx.x; // < 16384
    int i = u >> 6, m = u & 63;
    int hi = i >> 4, wi = i & 15;
    int mh = m >> 3, mw = m & 7;
    float acc[6] = {0.f, 0.f, 0.f, 0.f, 0.f, 0.f};
#pragma unroll
    for (int rh = 0; rh < 2; rh++)
#pragma unroll
        for (int rw = 0; rw < 2; rw++) {
            int jh = mh * 2 + rh, jw = mw * 2 + rw;
            int idx = (hi - jh + 15) * 31 + (wi - jw + 15);
            const float* tr = s_tab + idx * 6;
#pragma unroll
            for (int n = 0; n < 6; n++) acc[n] += tr[n];
        }
#pragma unroll
    for (int n = 0; n < 6; n++) s_rpb[n * 16384 + u] = acc[n] * 0.25f;
}

// ================= DFE stage 1: y1 = leaky(x @ W1 + b1)  (180 -> 36) =================
// block: 128 rows, thread tile 4r x 5c (32 row-groups x 8 col-groups, N padded to 40)
__global__ __launch_bounds__(256, 1) void k_dfe1(const float* __restrict__ x,
                                                 const float* __restrict__ w,
                                                 const float* __restrict__ b) {
    extern __shared__ float sm[];
    float* xs = sm;              // 128*180
    float* ws = sm + 128 * 180;  // 180*40 (padded)
    int row0 = blockIdx.x * 128;
    int tid = threadIdx.x;
    for (int t = tid; t < 128 * 180; t += 256) xs[t] = x[row0 * 180 + t];
    for (int t = tid; t < 180 * 40; t += 256) {
        int k = t / 40, c = t - k * 40;
        ws[t] = (c < 36) ? w[k * 36 + c] : 0.f;
    }
    __syncthreads();
    int tr = tid >> 3, tc = tid & 7;
    int r0 = tr * 4, c0 = tc * 5;
    float acc[4][5];
#pragma unroll
    for (int i = 0; i < 4; i++)
#pragma unroll
        for (int j = 0; j < 5; j++) acc[i][j] = 0.f;
    for (int k = 0; k < 180; k++) {
        float av[4];
#pragma unroll
        for (int i = 0; i < 4; i++) av[i] = xs[(r0 + i) * 180 + k];
#pragma unroll
        for (int j = 0; j < 5; j++) {
            float bv = ws[k * 40 + c0 + j];
#pragma unroll
            for (int i = 0; i < 4; i++) acc[i][j] = fmaf(av[i], bv, acc[i][j]);
        }
    }
#pragma unroll
    for (int j = 0; j < 5; j++) {
        int c = c0 + j;
        if (c < 36) {
            float bc = b[c];
#pragma unroll
            for (int i = 0; i < 4; i++) {
                float v = acc[i][j] + bc;
                s_y1[(row0 + r0 + i) * 36 + c] = v > 0.f ? v : 0.2f * v;
            }
        }
    }
}

// ================= DFE stage 2: 3x3 SAME conv (36 -> 36) + leaky =================
// block: 16x16 pixel tile; thread: 4 pixels x 9 out-channels
__global__ __launch_bounds__(256, 2) void k_conv(const float* __restrict__ w,
                                                 const float* __restrict__ bias) {
    extern __shared__ float sm[];
    float* hs = sm;                // 18*18*37 (padded channel stride)
    float* ws = sm + 18 * 18 * 37; // 9*36*36
    int bImg = blockIdx.z, ty = blockIdx.y, tx = blockIdx.x;
    int tid = threadIdx.x;
    int y0 = ty * 16 - 1, x0 = tx * 16 - 1;
    for (int t = tid; t < 18 * 18 * 36; t += 256) {
        int pix = t / 36, ci = t - pix * 36;
        int py = pix / 18, px = pix - py * 18;
        int gy = y0 + py, gx = x0 + px;
        float v = 0.f;
        if (gy >= 0 && gy < 256 && gx >= 0 && gx < 256)
            v = s_y1[((bImg * 256 + gy) * 256 + gx) * 36 + ci];
        hs[pix * 37 + ci] = v;
    }
    for (int t = tid; t < 9 * 36 * 36; t += 256) ws[t] = w[t];
    __syncthreads();

    int pg = tid >> 2, cg = tid & 3;
    int ch0 = cg * 9;
    float acc[4][9];
#pragma unroll
    for (int i = 0; i < 4; i++)
#pragma unroll
        for (int j = 0; j < 9; j++) acc[i][j] = 0.f;
#pragma unroll
    for (int kh = 0; kh < 3; kh++)
#pragma unroll
        for (int kw = 0; kw < 3; kw++) {
            for (int ci = 0; ci < 36; ci++) {
                float vv[4];
#pragma unroll
                for (int ip = 0; ip < 4; ip++) {
                    int p = pg * 4 + ip;
                    int py = p >> 4, px = p & 15;
                    vv[ip] = hs[((py + kh) * 18 + px + kw) * 37 + ci];
                }
                const float* wr = ws + ((kh * 3 + kw) * 36 + ci) * 36 + ch0;
#pragma unroll
                for (int jc = 0; jc < 9; jc++) {
                    float wv = wr[jc];
#pragma unroll
                    for (int ip = 0; ip < 4; ip++) acc[ip][jc] = fmaf(vv[ip], wv, acc[ip][jc]);
                }
            }
        }
#pragma unroll
    for (int ip = 0; ip < 4; ip++) {
        int p = pg * 4 + ip;
        int py = p >> 4, px = p & 15;
        int gaddr = ((bImg * 256 + ty * 16 + py) * 256 + tx * 16 + px) * 36;
#pragma unroll
        for (int jc = 0; jc < 9; jc++) {
            int co = ch0 + jc;
            float v = acc[ip][jc] + bias[co];
            s_y2[gaddr + co] = v > 0.f ? v : 0.2f * v;
        }
    }
}

// ============ DFE stage 3: qv = (y2@W3+b3) * (x@Wl+bl)  (fused, 64 rows/block) ============
__global__ __launch_bounds__(256, 1) void k_dfe3(const float* __restrict__ x,
                                                 const float* __restrict__ w3, const float* __restrict__ b3,
                                                 const float* __restrict__ wl, const float* __restrict__ bl) {
    extern __shared__ float sm[];
    float* y2s = sm;                 // 64*36
    float* xs  = y2s + 64 * 36;      // 64*180
    float* w3s = xs + 64 * 180;      // 36*192 padded
    float* wls = w3s + 36 * 192;     // 180*192 padded
    int row0 = blockIdx.x * 64;
    int tid = threadIdx.x;
    for (int t = tid; t < 64 * 36; t += 256) y2s[t] = s_y2[row0 * 36 + t];
    for (int t = tid; t < 64 * 180; t += 256) xs[t] = x[row0 * 180 + t];
    for (int t = tid; t < 36 * 192; t += 256) {
        int k = t / 192, c = t - k * 192;
        w3s[t] = (c < 180) ? w3[k * 180 + c] : 0.f;
    }
    for (int t = tid; t < 180 * 192; t += 256) {
        int k = t / 192, c = t - k * 192;
        wls[t] = (c < 180) ? wl[k * 180 + c] : 0.f;
    }
    __syncthreads();

    int tr = tid >> 5, tc = tid & 31;
    int r0 = tr * 8, c0 = tc * 6;
    float accA[8][6], accD[8][6];
#pragma unroll
    for (int i = 0; i < 8; i++)
#pragma unroll
        for (int j = 0; j < 6; j++) { accA[i][j] = 0.f; accD[i][j] = 0.f; }
    for (int k = 0; k < 36; k++) {
        float av[8];
#pragma unroll
        for (int i = 0; i < 8; i++) av[i] = y2s[(r0 + i) * 36 + k];
#pragma unroll
        for (int j = 0; j < 6; j++) {
            float bv = w3s[k * 192 + c0 + j];
#pragma unroll
            for (int i = 0; i < 8; i++) accA[i][j] = fmaf(av[i], bv, accA[i][j]);
        }
    }
    for (int k = 0; k < 180; k++) {
        float av[8];
#pragma unroll
        for (int i = 0; i < 8; i++) av[i] = xs[(r0 + i) * 180 + k];
#pragma unroll
        for (int j = 0; j < 6; j++) {
            float bv = wls[k * 192 + c0 + j];
#pragma unroll
            for (int i = 0; i < 8; i++) accD[i][j] = fmaf(av[i], bv, accD[i][j]);
        }
    }
#pragma unroll
    for (int j = 0; j < 6; j++) {
        int c = c0 + j;
        if (c < 180) {
            float bc = b3[c], dc = bl[c];
#pragma unroll
            for (int i = 0; i < 8; i++)
                s_qv[(row0 + r0 + i) * 180 + c] = (accA[i][j] + bc) * (accD[i][j] + dc);
        }
    }
}

// ================= vp: downsampled v  (512, 6, 64, 15) =================
__global__ void k_vp(const float* __restrict__ sl_w, const float* __restrict__ sl_b) {
    int u = blockIdx.x * blockDim.x + threadIdx.x;
    if (u >= NWIN * 384) return;
    int w = u / 384;
    int rem = u - w * 384;
    int n = rem >> 6, m = rem & 63;
    int b = w >> 8, wh = (w >> 4) & 15, ww = w & 15;
    int mh = m >> 3, mw = m & 7;
    int gh = wh * 16 + mh * 2, gw = ww * 16 + mw * 2;
    const float* q00 = s_qv + ((b * 256 + gh) * 256 + gw) * 180 + 90 + n * 15;
    const float* q01 = q00 + 180;
    const float* q10 = q00 + 256 * 180;
    const float* q11 = q10 + 180;
    float w0 = sl_w[0], w1 = sl_w[1], w2 = sl_w[2], w3 = sl_w[3], bb = sl_b[0];
    float* out = s_vp + ((w * 6 + n) * 64 + m) * 15;
#pragma unroll
    for (int c = 0; c < 15; c++)
        out[c] = bb + q00[c] * w0 + q01[c] * w1 + q10[c] * w2 + q11[c] * w3;
}

// ================= spatial correlation per (window, head) =================
__global__ __launch_bounds__(256, 4) void k_sp() {
    __shared__ float vps[960];
    int blk = blockIdx.x;
    int w = blk / 6, n = blk - w * 6;
    int b = w >> 8, wh = (w >> 4) & 15, ww = w & 15;
    int tid = threadIdx.x;
    const float* vsrc = s_vp + (w * 6 + n) * 960;
    for (int t = tid; t < 960; t += 256) vps[t] = vsrc[t];
    __syncthreads();

    int l = tid;
    int gh = wh * 16 + (l >> 4), gw = ww * 16 + (l & 15);
    int gpix = ((b * 256 + gh) * 256 + gw) * 180;
    float qr[15];
#pragma unroll
    for (int c = 0; c < 15; c++) qr[c] = s_qv[gpix + n * 15 + c];

    float co[64];
    const float* rp = s_rpb + n * 16384 + l * 64;
#pragma unroll 8
    for (int m = 0; m < 64; m++) {
        float a = 0.f;
#pragma unroll
        for (int c = 0; c < 15; c++) a = fmaf(qr[c], vps[m * 15 + c], a);
        co[m] = a * (1.0f / 15.0f) + rp[m];
    }
#pragma unroll
    for (int c = 0; c < 15; c++) {
        float a = 0.f;
#pragma unroll 16
        for (int m = 0; m < 64; m++) a = fmaf(co[m], vps[m * 15 + c], a);
        s_cat[gpix + n * 15 + c] = a;
    }
}

// ================= channel correlation (fused cc + x_ch), one block per window =================
#define CHP 181
__global__ __launch_bounds__(256, 1) void k_ch() {
    extern __shared__ float sm[];
    float* qvs = sm;            // 256 * 181
    float* ccs = sm + 256 * CHP; // 90*90
    int w = blockIdx.x;
    int b = w >> 8, wh = (w >> 4) & 15, ww = w & 15;
    int tid = threadIdx.x;

    for (int t = tid; t < 256 * 180; t += 256) {
        int l = t / 180, ch = t - l * 180;
        int gh = wh * 16 + (l >> 4), gw = ww * 16 + (l & 15);
        qvs[l * CHP + ch] = s_qv[((b * 256 + gh) * 256 + gw) * 180 + ch];
    }
    __syncthreads();

    // cc[c][d] = (1/256) * sum_l qc[l][c] * vc[l][d]
    {
        int tc = tid >> 4, td = tid & 15;
        float acc[6][6];
#pragma unroll
        for (int i = 0; i < 6; i++)
#pragma unroll
            for (int j = 0; j < 6; j++) acc[i][j] = 0.f;
        for (int l = 0; l < 256; l++) {
            float qa[6], vb[6];
#pragma unroll
            for (int i = 0; i < 6; i++) {
                int c = tc + 16 * i;
                qa[i] = (c < 90) ? qvs[l * CHP + c] : 0.f;
            }
#pragma unroll
            for (int j = 0; j < 6; j++) {
                int d = td + 16 * j;
                vb[j] = (d < 90) ? qvs[l * CHP + 90 + d] : 0.f;
            }
#pragma unroll
            for (int i = 0; i < 6; i++)
#pragma unroll
                for (int j = 0; j < 6; j++) acc[i][j] = fmaf(qa[i], vb[j], acc[i][j]);
        }
#pragma unroll
        for (int i = 0; i < 6; i++)
#pragma unroll
            for (int j = 0; j < 6; j++) {
                int c = tc + 16 * i, d = td + 16 * j;
                if (c < 90 && d < 90) ccs[c * 90 + d] = acc[i][j] * (1.f / 256.f);
            }
    }
    __syncthreads();

    // x_ch[l][c] = sum_d cc[c][d] * vc[l][d]
    {
        int tl = tid & 31, tc2 = tid >> 5;
        float acc[8][12];
#pragma unroll
        for (int i = 0; i < 8; i++)
#pragma unroll
            for (int j = 0; j < 12; j++) acc[i][j] = 0.f;
        for (int d = 0; d < 90; d++) {
            float vv[8];
#pragma unroll
            for (int il = 0; il < 8; il++) vv[il] = qvs[(tl + 32 * il) * CHP + 90 + d];
#pragma unroll
            for (int jc = 0; jc < 12; jc++) {
                int c = tc2 + 8 * jc;
                float cv = (c < 90) ? ccs[c * 90 + d] : 0.f;
#pragma unroll
                for (int il = 0; il < 8; il++) acc[il][jc] = fmaf(vv[il], cv, acc[il][jc]);
            }
        }
#pragma unroll
        for (int jc = 0; jc < 12; jc++) {
            int c = tc2 + 8 * jc;
            if (c < 90) {
#pragma unroll
                for (int il = 0; il < 8; il++) {
                    int l = tl + 32 * il;
                    int gh = wh * 16 + (l >> 4), gw = ww * 16 + (l & 15);
                    s_cat[((b * 256 + gh) * 256 + gw) * 180 + 90 + c] = acc[il][jc];
                }
            }
        }
    }
}

// ================= final projection: out = cat @ Wp + bp =================
__global__ __launch_bounds__(256, 1) void k_proj(const float* __restrict__ wp,
                                                 const float* __restrict__ bp,
                                                 float* __restrict__ out) {
    extern __shared__ float sm[];
    float* xs = sm;              // 64*180
    float* ws = sm + 64 * 180;   // 180*192 padded
    int row0 = blockIdx.x * 64;
    int tid = threadIdx.x;
    for (int t = tid; t < 64 * 180; t += 256) xs[t] = s_cat[row0 * 180 + t];
    for (int t = tid; t < 180 * 192; t += 256) {
        int k = t / 192, c = t - k * 192;
        ws[t] = (c < 180) ? wp[k * 180 + c] : 0.f;
    }
    __syncthreads();

    int tr = tid >> 5, tc = tid & 31;
    int r0 = tr * 8, c0 = tc * 6;
    float acc[8][6];
#pragma unroll
    for (int i = 0; i < 8; i++)
#pragma unroll
        for (int j = 0; j < 6; j++) acc[i][j] = 0.f;
    for (int k = 0; k < 180; k++) {
        float av[8];
#pragma unroll
        for (int i = 0; i < 8; i++) av[i] = xs[(r0 + i) * 180 + k];
#pragma unroll
        for (int j = 0; j < 6; j++) {
            float bv = ws[k * 192 + c0 + j];
#pragma unroll
            for (int i = 0; i < 8; i++) acc[i][j] = fmaf(av[i], bv, acc[i][j]);
        }
    }
#pragma unroll
    for (int j = 0; j < 6; j++) {
        int c = c0 + j;
        if (c < 180) {
            float bc = bp[c];
#pragma unroll
            for (int i = 0; i < 8; i++)
                out[(row0 + r0 + i) * 180 + c] = acc[i][j] + bc;
        }
    }
}

// ================= launch =================
extern "C" void kernel_launch(void* const* d_in, const int* in_sizes, int n_in,
                              void* d_out, int out_size) {
    const float* x        = (const float*)d_in[0];
    const float* conv1_w  = (const float*)d_in[1];
    const float* conv1_b  = (const float*)d_in[2];
    const float* conv2_w  = (const float*)d_in[3];
    const float* conv2_b  = (const float*)d_in[4];
    const float* conv3_w  = (const float*)d_in[5];
    const float* conv3_b  = (const float*)d_in[6];
    const float* dfe_lw   = (const float*)d_in[7];
    const float* dfe_lb   = (const float*)d_in[8];
    const float* sl_w     = (const float*)d_in[9];
    const float* sl_b     = (const float*)d_in[10];
    const float* pos_w    = (const float*)d_in[11];
    const float* pos_b    = (const float*)d_in[12];
    const float* ln1_g    = (const float*)d_in[13];
    const float* ln1_b    = (const float*)d_in[14];
    const float* mlp1_w   = (const float*)d_in[15];
    const float* mlp1_b   = (const float*)d_in[16];
    const float* ln2_g    = (const float*)d_in[17];
    const float* ln2_b    = (const float*)d_in[18];
    const float* mlp2_w   = (const float*)d_in[19];
    const float* mlp2_b   = (const float*)d_in[20];
    const float* ln3_g    = (const float*)d_in[21];
    const float* ln3_b    = (const float*)d_in[22];
    const float* mlp3_w   = (const float*)d_in[23];
    const float* mlp3_b   = (const float*)d_in[24];
    const float* proj_w   = (const float*)d_in[25];
    const float* proj_b   = (const float*)d_in[26];
    float* out = (float*)d_out;

    const int SM1 = (128 * 180 + 180 * 40) * 4;          // 120,960
    const int SM2 = (18 * 18 * 37 + 9 * 36 * 36) * 4;    // 94,608
    const int SM3 = (64 * 36 + 64 * 180 + 36 * 192 + 180 * 192) * 4; // 221,184
    const int SMC = (256 * CHP + 90 * 90) * 4;           // 217,744
    const int SMP = (64 * 180 + 180 * 192) * 4;          // 184,320

    cudaFuncSetAttribute(k_dfe1, cudaFuncAttributeMaxDynamicSharedMemorySize, SM1);
    cudaFuncSetAttribute(k_conv, cudaFuncAttributeMaxDynamicSharedMemorySize, SM2);
    cudaFuncSetAttribute(k_dfe3, cudaFuncAttributeMaxDynamicSharedMemorySize, SM3);
    cudaFuncSetAttribute(k_ch,   cudaFuncAttributeMaxDynamicSharedMemorySize, SMC);
    cudaFuncSetAttribute(k_proj, cudaFuncAttributeMaxDynamicSharedMemorySize, SMP);

    k_postab<<<4, 256>>>(pos_w, pos_b, ln1_g, ln1_b, mlp1_w, mlp1_b,
                         ln2_g, ln2_b, mlp2_w, mlp2_b, ln3_g, ln3_b, mlp3_w, mlp3_b);
    k_rpb<<<64, 256>>>();
    k_dfe1<<<PTOT / 128, 256, SM1>>>(x, conv1_w, conv1_b);
    k_conv<<<dim3(16, 16, 2), 256, SM2>>>(conv2_w, conv2_b);
    k_dfe3<<<PTOT / 64, 256, SM3>>>(x, conv3_w, conv3_b, dfe_lw, dfe_lb);
    k_vp<<<(NWIN * 384 + 255) / 256, 256>>>(sl_w, sl_b);
    k_sp<<<NWIN * 6, 256>>>();
    k_ch<<<NWIN, 256, SMC>>>();
    k_proj<<<PTOT / 64, 256, SMP>>>(proj_w, proj_b, out);
}

// round 2
// speedup vs baseline: 1.3198x; 1.3198x over previous
#include <cuda_runtime.h>
#include <math.h>

// ---------------- problem constants ----------------
#define BATCH 2
#define HH 256
#define WW_ 256
#define CC 180
#define C5 36
#define NHD 6
#define HD 15
#define L 256
#define ML 64
#define NWIN 512            // total windows (2 * 16 * 16)
#define PTOT (BATCH*HH*WW_) // 131072 pixels

// ---------------- device scratch (static, allowed) ----------------
__device__ float s_y1[PTOT * C5];
__device__ float s_y2[PTOT * C5];
__device__ float s_qv[PTOT * CC];
__device__ float s_cat[PTOT * CC];
__device__ float s_vp[NWIN * NHD * ML * HD];
__device__ float s_rpb[NHD * L * ML];
__device__ float s_tab[961 * NHD];

// ================= position-bias MLP table (961 x 6) =================
__global__ void k_postab(const float* __restrict__ pw, const float* __restrict__ pb,
                         const float* __restrict__ g1, const float* __restrict__ b1,
                         const float* __restrict__ m1w, const float* __restrict__ m1b,
                         const float* __restrict__ g2, const float* __restrict__ b2,
                         const float* __restrict__ m2w, const float* __restrict__ m2b,
                         const float* __restrict__ g3, const float* __restrict__ b3,
                         const float* __restrict__ m3w, const float* __restrict__ m3b) {
    int t = blockIdx.x * blockDim.x + threadIdx.x;
    if (t >= 961) return;
    int a = t / 31, bcol = t - a * 31;
    float gx = (float)a - 15.f, gy = (float)bcol - 15.f;
    float p[11], q[11];
#pragma unroll
    for (int j = 0; j < 11; j++) p[j] = gx * pw[j] + gy * pw[11 + j] + pb[j];

    {
        float m = 0.f;
#pragma unroll
        for (int j = 0; j < 11; j++) m += p[j];
        m *= (1.f / 11.f);
        float v = 0.f;
#pragma unroll
        for (int j = 0; j < 11; j++) { float d = p[j] - m; v += d * d; }
        v *= (1.f / 11.f);
        float inv = 1.f / sqrtf(v + 1e-5f);
#pragma unroll
        for (int j = 0; j < 11; j++) {
            float h = (p[j] - m) * inv * g1[j] + b1[j];
            q[j] = h > 0.f ? h : 0.f;
        }
#pragma unroll
        for (int j = 0; j < 11; j++) {
            float acc = m1b[j];
#pragma unroll
            for (int k = 0; k < 11; k++) acc += q[k] * m1w[k * 11 + j];
            p[j] = acc;
        }
    }
    {
        float m = 0.f;
#pragma unroll
        for (int j = 0; j < 11; j++) m += p[j];
        m *= (1.f / 11.f);
        float v = 0.f;
#pragma unroll
        for (int j = 0; j < 11; j++) { float d = p[j] - m; v += d * d; }
        v *= (1.f / 11.f);
        float inv = 1.f / sqrtf(v + 1e-5f);
#pragma unroll
        for (int j = 0; j < 11; j++) {
            float h = (p[j] - m) * inv * g2[j] + b2[j];
            q[j] = h > 0.f ? h : 0.f;
        }
#pragma unroll
        for (int j = 0; j < 11; j++) {
            float acc = m2b[j];
#pragma unroll
            for (int k = 0; k < 11; k++) acc += q[k] * m2w[k * 11 + j];
            p[j] = acc;
        }
    }
    {
        float m = 0.f;
#pragma unroll
        for (int j = 0; j < 11; j++) m += p[j];
        m *= (1.f / 11.f);
        float v = 0.f;
#pragma unroll
        for (int j = 0; j < 11; j++) { float d = p[j] - m; v += d * d; }
        v *= (1.f / 11.f);
        float inv = 1.f / sqrtf(v + 1e-5f);
#pragma unroll
        for (int j = 0; j < 11; j++) {
            float h = (p[j] - m) * inv * g3[j] + b3[j];
            q[j] = h > 0.f ? h : 0.f;
        }
#pragma unroll
        for (int n = 0; n < 6; n++) {
            float acc = m3b[n];
#pragma unroll
            for (int k = 0; k < 11; k++) acc += q[k] * m3w[k * 6 + n];
            s_tab[t * 6 + n] = acc;
        }
    }
}

// ================= rpb gather/average: (6, 256, 64) =================
__global__ void k_rpb() {
    int u = blockIdx.x * blockDim.x + threadIdx.x; // < 16384
    int i = u >> 6, m = u & 63;
    int hi = i >> 4, wi = i & 15;
    int mh = m >> 3, mw = m & 7;
    float acc[6] = {0.f, 0.f, 0.f, 0.f, 0.f, 0.f};
#pragma unroll
    for (int rh = 0; rh < 2; rh++)
#pragma unroll
        for (int rw = 0; rw < 2; rw++) {
            int jh = mh * 2 + rh, jw = mw * 2 + rw;
            int idx = (hi - jh + 15) * 31 + (wi - jw + 15);
            const float* tr = s_tab + idx * 6;
#pragma unroll
            for (int n = 0; n < 6; n++) acc[n] += tr[n];
        }
#pragma unroll
    for (int n = 0; n < 6; n++) s_rpb[n * 16384 + u] = acc[n] * 0.25f;
}

// ================= DFE stage 1: y1 = leaky(x @ W1 + b1)  (180 -> 36) =================
__global__ __launch_bounds__(256, 1) void k_dfe1(const float* __restrict__ x,
                                                 const float* __restrict__ w,
                                                 const float* __restrict__ b) {
    extern __shared__ float sm[];
    float* xs = sm;              // 128*180
    float* ws = sm + 128 * 180;  // 180*40 (padded)
    int row0 = blockIdx.x * 128;
    int tid = threadIdx.x;
    {
        const float4* src = (const float4*)(x + row0 * 180);
        float4* dst = (float4*)xs;
        for (int t = tid; t < 128 * 45; t += 256) dst[t] = src[t];
    }
    for (int t = tid; t < 180 * 40; t += 256) {
        int k = t / 40, c = t - k * 40;
        ws[t] = (c < 36) ? w[k * 36 + c] : 0.f;
    }
    __syncthreads();
    int tr = tid >> 3, tc = tid & 7;
    int r0 = tr * 4, c0 = tc * 5;
    float acc[4][5];
#pragma unroll
    for (int i = 0; i < 4; i++)
#pragma unroll
        for (int j = 0; j < 5; j++) acc[i][j] = 0.f;
    for (int k = 0; k < 180; k++) {
        float av[4];
#pragma unroll
        for (int i = 0; i < 4; i++) av[i] = xs[(r0 + i) * 180 + k];
#pragma unroll
        for (int j = 0; j < 5; j++) {
            float bv = ws[k * 40 + c0 + j];
#pragma unroll
            for (int i = 0; i < 4; i++) acc[i][j] = fmaf(av[i], bv, acc[i][j]);
        }
    }
#pragma unroll
    for (int j = 0; j < 5; j++) {
        int c = c0 + j;
        if (c < 36) {
            float bc = b[c];
#pragma unroll
            for (int i = 0; i < 4; i++) {
                float v = acc[i][j] + bc;
                s_y1[(row0 + r0 + i) * 36 + c] = v > 0.f ? v : 0.2f * v;
            }
        }
    }
}

// ================= DFE stage 2: 3x3 SAME conv (36 -> 36) + leaky =================
__global__ __launch_bounds__(256, 2) void k_conv(const float* __restrict__ w,
                                                 const float* __restrict__ bias) {
    extern __shared__ float sm[];
    float* hs = sm;                // 18*18*37 (padded channel stride)
    float* ws = sm + 18 * 18 * 37; // 9*36*36
    int bImg = blockIdx.z, ty = blockIdx.y, tx = blockIdx.x;
    int tid = threadIdx.x;
    int y0 = ty * 16 - 1, x0 = tx * 16 - 1;
    for (int t = tid; t < 18 * 18 * 36; t += 256) {
        int pix = t / 36, ci = t - pix * 36;
        int py = pix / 18, px = pix - py * 18;
        int gy = y0 + py, gx = x0 + px;
        float v = 0.f;
        if (gy >= 0 && gy < 256 && gx >= 0 && gx < 256)
            v = s_y1[((bImg * 256 + gy) * 256 + gx) * 36 + ci];
        hs[pix * 37 + ci] = v;
    }
    for (int t = tid; t < 9 * 36 * 36; t += 256) ws[t] = w[t];
    __syncthreads();

    int pg = tid >> 2, cg = tid & 3;
    int ch0 = cg * 9;
    float acc[4][9];
#pragma unroll
    for (int i = 0; i < 4; i++)
#pragma unroll
        for (int j = 0; j < 9; j++) acc[i][j] = 0.f;
#pragma unroll
    for (int kh = 0; kh < 3; kh++)
#pragma unroll
        for (int kw = 0; kw < 3; kw++) {
            for (int ci = 0; ci < 36; ci++) {
                float vv[4];
#pragma unroll
                for (int ip = 0; ip < 4; ip++) {
                    int p = pg * 4 + ip;
                    int py = p >> 4, px = p & 15;
                    vv[ip] = hs[((py + kh) * 18 + px + kw) * 37 + ci];
                }
                const float* wr = ws + ((kh * 3 + kw) * 36 + ci) * 36 + ch0;
#pragma unroll
                for (int jc = 0; jc < 9; jc++) {
                    float wv = wr[jc];
#pragma unroll
                    for (int ip = 0; ip < 4; ip++) acc[ip][jc] = fmaf(vv[ip], wv, acc[ip][jc]);
                }
            }
        }
#pragma unroll
    for (int ip = 0; ip < 4; ip++) {
        int p = pg * 4 + ip;
        int py = p >> 4, px = p & 15;
        int gaddr = ((bImg * 256 + ty * 16 + py) * 256 + tx * 16 + px) * 36;
#pragma unroll
        for (int jc = 0; jc < 9; jc++) {
            int co = ch0 + jc;
            float v = acc[ip][jc] + bias[co];
            s_y2[gaddr + co] = v > 0.f ? v : 0.2f * v;
        }
    }
}

// ============ DFE stage 3 (PERSISTENT): qv = (y2@W3+b3) * (x@Wl+bl) ============
// grid=148, 512 threads; weights resident in smem for whole kernel.
__global__ __launch_bounds__(512, 1) void k_dfe3(const float* __restrict__ x,
                                                 const float* __restrict__ w3, const float* __restrict__ b3,
                                                 const float* __restrict__ wl, const float* __restrict__ bl) {
    extern __shared__ float sm[];
    float* w3s = sm;                 // 36*192 padded
    float* wls = w3s + 36 * 192;     // 180*192 padded
    float* y2s = wls + 180 * 192;    // 64*36
    float* xs  = y2s + 64 * 36;      // 64*180
    int tid = threadIdx.x;
    for (int t = tid; t < 36 * 192; t += 512) {
        int k = t / 192, c = t - k * 192;
        w3s[t] = (c < 180) ? w3[k * 180 + c] : 0.f;
    }
    for (int t = tid; t < 180 * 192; t += 512) {
        int k = t / 192, c = t - k * 192;
        wls[t] = (c < 180) ? wl[k * 180 + c] : 0.f;
    }
    int tr = tid >> 5, tc = tid & 31;
    int r0 = tr * 4, c0 = tc * 6;

    for (int tile = blockIdx.x; tile < PTOT / 64; tile += gridDim.x) {
        int row0 = tile * 64;
        __syncthreads();
        {
            const float4* src = (const float4*)(x + row0 * 180);
            float4* dst = (float4*)xs;
            for (int t = tid; t < 64 * 45; t += 512) dst[t] = src[t];
            const float4* ys = (const float4*)(s_y2 + row0 * 36);
            float4* yd = (float4*)y2s;
            for (int t = tid; t < 64 * 9; t += 512) yd[t] = ys[t];
        }
        __syncthreads();

        float accA[4][6], accD[4][6];
#pragma unroll
        for (int i = 0; i < 4; i++)
#pragma unroll
            for (int j = 0; j < 6; j++) { accA[i][j] = 0.f; accD[i][j] = 0.f; }
        for (int k = 0; k < 36; k++) {
            float av[4];
#pragma unroll
            for (int i = 0; i < 4; i++) av[i] = y2s[(r0 + i) * 36 + k];
#pragma unroll
            for (int j = 0; j < 6; j++) {
                float bv = w3s[k * 192 + c0 + j];
#pragma unroll
                for (int i = 0; i < 4; i++) accA[i][j] = fmaf(av[i], bv, accA[i][j]);
            }
        }
        for (int k = 0; k < 180; k++) {
            float av[4];
#pragma unroll
            for (int i = 0; i < 4; i++) av[i] = xs[(r0 + i) * 180 + k];
#pragma unroll
            for (int j = 0; j < 6; j++) {
                float bv = wls[k * 192 + c0 + j];
#pragma unroll
                for (int i = 0; i < 4; i++) accD[i][j] = fmaf(av[i], bv, accD[i][j]);
            }
        }
#pragma unroll
        for (int j = 0; j < 6; j++) {
            int c = c0 + j;
            if (c < 180) {
                float bc = b3[c], dc = bl[c];
#pragma unroll
                for (int i = 0; i < 4; i++)
                    s_qv[(row0 + r0 + i) * 180 + c] = (accA[i][j] + bc) * (accD[i][j] + dc);
            }
        }
    }
}

// ================= vp: downsampled v  (512, 6, 64, 15) =================
__global__ void k_vp(const float* __restrict__ sl_w, const float* __restrict__ sl_b) {
    int u = blockIdx.x * blockDim.x + threadIdx.x;
    if (u >= NWIN * 384) return;
    int w = u / 384;
    int rem = u - w * 384;
    int n = rem >> 6, m = rem & 63;
    int b = w >> 8, wh = (w >> 4) & 15, ww = w & 15;
    int mh = m >> 3, mw = m & 7;
    int gh = wh * 16 + mh * 2, gw = ww * 16 + mw * 2;
    const float* q00 = s_qv + ((b * 256 + gh) * 256 + gw) * 180 + 90 + n * 15;
    const float* q01 = q00 + 180;
    const float* q10 = q00 + 256 * 180;
    const float* q11 = q10 + 180;
    float w0 = sl_w[0], w1 = sl_w[1], w2 = sl_w[2], w3 = sl_w[3], bb = sl_b[0];
    float* out = s_vp + ((w * 6 + n) * 64 + m) * 15;
#pragma unroll
    for (int c = 0; c < 15; c++)
        out[c] = bb + q00[c] * w0 + q01[c] * w1 + q10[c] * w2 + q11[c] * w3;
}

// ================= spatial correlation per (window, head) — chunked, no spills =================
__global__ __launch_bounds__(256, 3) void k_sp() {
    __shared__ float vps[960];
    int blk = blockIdx.x;
    int w = blk / 6, n = blk - w * 6;
    int b = w >> 8, wh = (w >> 4) & 15, ww = w & 15;
    int tid = threadIdx.x;
    const float* vsrc = s_vp + (w * 6 + n) * 960;
    for (int t = tid; t < 960; t += 256) vps[t] = vsrc[t];
    __syncthreads();

    int l = tid;
    int gh = wh * 16 + (l >> 4), gw = ww * 16 + (l & 15);
    int gpix = ((b * 256 + gh) * 256 + gw) * 180;
    float qr[15];
#pragma unroll
    for (int c = 0; c < 15; c++) qr[c] = s_qv[gpix + n * 15 + c];

    float out[15];
#pragma unroll
    for (int c = 0; c < 15; c++) out[c] = 0.f;
    const float* rp = s_rpb + n * 16384 + l * 64;

#pragma unroll
    for (int ch = 0; ch < 4; ch++) {
        float co[16];
#pragma unroll
        for (int mm = 0; mm < 16; mm++) {
            int m = ch * 16 + mm;
            float a = 0.f;
#pragma unroll
            for (int c = 0; c < 15; c++) a = fmaf(qr[c], vps[m * 15 + c], a);
            co[mm] = a * (1.0f / 15.0f) + rp[m];
        }
#pragma unroll
        for (int c = 0; c < 15; c++) {
            float a = out[c];
#pragma unroll
            for (int mm = 0; mm < 16; mm++)
                a = fmaf(co[mm], vps[(ch * 16 + mm) * 15 + c], a);
            out[c] = a;
        }
    }
#pragma unroll
    for (int c = 0; c < 15; c++) s_cat[gpix + n * 15 + c] = out[c];
}

// ================= channel correlation (fused cc + x_ch), one block per window, 512 thr =================
#define CHP 181
__global__ __launch_bounds__(512, 1) void k_ch() {
    extern __shared__ float sm[];
    float* qvs = sm;             // 256 * 181
    float* ccs = sm + 256 * CHP; // 90*90
    int w = blockIdx.x;
    int b = w >> 8, wh = (w >> 4) & 15, ww = w & 15;
    int tid = threadIdx.x;

    // vectorized global load, scalar smem store (stride 181 keeps LDS conflict-free)
    for (int t = tid; t < 256 * 45; t += 512) {
        int l = t / 45, j = t - l * 45;
        int gh = wh * 16 + (l >> 4), gw = ww * 16 + (l & 15);
        float4 v = *(const float4*)(s_qv + ((b * 256 + gh) * 256 + gw) * 180 + j * 4);
        float* dst = qvs + l * CHP + j * 4;
        dst[0] = v.x; dst[1] = v.y; dst[2] = v.z; dst[3] = v.w;
    }
    __syncthreads();

    // cc[c][d] = (1/256) * sum_l qc[l][c] * vc[l][d]
    {
        int tc = tid >> 5, td = tid & 31;    // 16 c-groups x 32 d-groups
        float acc[6][3];
#pragma unroll
        for (int i = 0; i < 6; i++)
#pragma unroll
            for (int j = 0; j < 3; j++) acc[i][j] = 0.f;
        for (int l = 0; l < 256; l++) {
            float qa[6], vb[3];
#pragma unroll
            for (int i = 0; i < 6; i++) {
                int c = tc + 16 * i;
                qa[i] = (c < 90) ? qvs[l * CHP + c] : 0.f;
            }
#pragma unroll
            for (int j = 0; j < 3; j++) {
                int d = td + 32 * j;
                vb[j] = (d < 90) ? qvs[l * CHP + 90 + d] : 0.f;
            }
#pragma unroll
            for (int i = 0; i < 6; i++)
#pragma unroll
                for (int j = 0; j < 3; j++) acc[i][j] = fmaf(qa[i], vb[j], acc[i][j]);
        }
#pragma unroll
        for (int i = 0; i < 6; i++)
#pragma unroll
            for (int j = 0; j < 3; j++) {
                int c = tc + 16 * i, d = td + 32 * j;
                if (c < 90 && d < 90) ccs[c * 90 + d] = acc[i][j] * (1.f / 256.f);
            }
    }
    __syncthreads();

    // x_ch[l][c] = sum_d cc[c][d] * vc[l][d]
    {
        int tl = tid & 31, tc2 = tid >> 5;   // 32 l-groups x 16 c-groups
        float acc[8][6];
#pragma unroll
        for (int i = 0; i < 8; i++)
#pragma unroll
            for (int j = 0; j < 6; j++) acc[i][j] = 0.f;
        for (int d = 0; d < 90; d++) {
            float vv[8];
#pragma unroll
            for (int il = 0; il < 8; il++) vv[il] = qvs[(tl + 32 * il) * CHP + 90 + d];
#pragma unroll
            for (int jc = 0; jc < 6; jc++) {
                int c = tc2 + 16 * jc;
                float cv = (c < 90) ? ccs[c * 90 + d] : 0.f;
#pragma unroll
                for (int il = 0; il < 8; il++) acc[il][jc] = fmaf(vv[il], cv, acc[il][jc]);
            }
        }
#pragma unroll
        for (int jc = 0; jc < 6; jc++) {
            int c = tc2 + 16 * jc;
            if (c < 90) {
#pragma unroll
                for (int il = 0; il < 8; il++) {
                    int l = tl + 32 * il;
                    int gh = wh * 16 + (l >> 4), gw = ww * 16 + (l & 15);
                    s_cat[((b * 256 + gh) * 256 + gw) * 180 + 90 + c] = acc[il][jc];
                }
            }
        }
    }
}

// ============ final projection (PERSISTENT): out = cat @ Wp + bp ============
__global__ __launch_bounds__(512, 1) void k_proj(const float* __restrict__ wp,
                                                 const float* __restrict__ bp,
                                                 float* __restrict__ out) {
    extern __shared__ float sm[];
    float* ws = sm;              // 180*192 padded
    float* xs = sm + 180 * 192;  // 64*180
    int tid = threadIdx.x;
    for (int t = tid; t < 180 * 192; t += 512) {
        int k = t / 192, c = t - k * 192;
        ws[t] = (c < 180) ? wp[k * 180 + c] : 0.f;
    }
    int tr = tid >> 5, tc = tid & 31;
    int r0 = tr * 4, c0 = tc * 6;

    for (int tile = blockIdx.x; tile < PTOT / 64; tile += gridDim.x) {
        int row0 = tile * 64;
        __syncthreads();
        {
            const float4* src = (const float4*)(s_cat + row0 * 180);
            float4* dst = (float4*)xs;
            for (int t = tid; t < 64 * 45; t += 512) dst[t] = src[t];
        }
        __syncthreads();

        float acc[4][6];
#pragma unroll
        for (int i = 0; i < 4; i++)
#pragma unroll
            for (int j = 0; j < 6; j++) acc[i][j] = 0.f;
        for (int k = 0; k < 180; k++) {
            float av[4];
#pragma unroll
            for (int i = 0; i < 4; i++) av[i] = xs[(r0 + i) * 180 + k];
#pragma unroll
            for (int j = 0; j < 6; j++) {
                float bv = ws[k * 192 + c0 + j];
#pragma unroll
                for (int i = 0; i < 4; i++) acc[i][j] = fmaf(av[i], bv, acc[i][j]);
            }
        }
#pragma unroll
        for (int j = 0; j < 6; j++) {
            int c = c0 + j;
            if (c < 180) {
                float bc = bp[c];
#pragma unroll
                for (int i = 0; i < 4; i++)
                    out[(row0 + r0 + i) * 180 + c] = acc[i][j] + bc;
            }
        }
    }
}

// ================= launch =================
extern "C" void kernel_launch(void* const* d_in, const int* in_sizes, int n_in,
                              void* d_out, int out_size) {
    const float* x        = (const float*)d_in[0];
    const float* conv1_w  = (const float*)d_in[1];
    const float* conv1_b  = (const float*)d_in[2];
    const float* conv2_w  = (const float*)d_in[3];
    const float* conv2_b  = (const float*)d_in[4];
    const float* conv3_w  = (const float*)d_in[5];
    const float* conv3_b  = (const float*)d_in[6];
    const float* dfe_lw   = (const float*)d_in[7];
    const float* dfe_lb   = (const float*)d_in[8];
    const float* sl_w     = (const float*)d_in[9];
    const float* sl_b     = (const float*)d_in[10];
    const float* pos_w    = (const float*)d_in[11];
    const float* pos_b    = (const float*)d_in[12];
    const float* ln1_g    = (const float*)d_in[13];
    const float* ln1_b    = (const float*)d_in[14];
    const float* mlp1_w   = (const float*)d_in[15];
    const float* mlp1_b   = (const float*)d_in[16];
    const float* ln2_g    = (const float*)d_in[17];
    const float* ln2_b    = (const float*)d_in[18];
    const float* mlp2_w   = (const float*)d_in[19];
    const float* mlp2_b   = (const float*)d_in[20];
    const float* ln3_g    = (const float*)d_in[21];
    const float* ln3_b    = (const float*)d_in[22];
    const float* mlp3_w   = (const float*)d_in[23];
    const float* mlp3_b   = (const float*)d_in[24];
    const float* proj_w   = (const float*)d_in[25];
    const float* proj_b   = (const float*)d_in[26];
    float* out = (float*)d_out;

    const int SM1 = (128 * 180 + 180 * 40) * 4;
    const int SM2 = (18 * 18 * 37 + 9 * 36 * 36) * 4;
    const int SM3 = (36 * 192 + 180 * 192 + 64 * 36 + 64 * 180) * 4;
    const int SMC = (256 * CHP + 90 * 90) * 4;
    const int SMP = (180 * 192 + 64 * 180) * 4;

    cudaFuncSetAttribute(k_dfe1, cudaFuncAttributeMaxDynamicSharedMemorySize, SM1);
    cudaFuncSetAttribute(k_conv, cudaFuncAttributeMaxDynamicSharedMemorySize, SM2);
    cudaFuncSetAttribute(k_dfe3, cudaFuncAttributeMaxDynamicSharedMemorySize, SM3);
    cudaFuncSetAttribute(k_ch,   cudaFuncAttributeMaxDynamicSharedMemorySize, SMC);
    cudaFuncSetAttribute(k_proj, cudaFuncAttributeMaxDynamicSharedMemorySize, SMP);

    k_postab<<<4, 256>>>(pos_w, pos_b, ln1_g, ln1_b, mlp1_w, mlp1_b,
                         ln2_g, ln2_b, mlp2_w, mlp2_b, ln3_g, ln3_b, mlp3_w, mlp3_b);
    k_rpb<<<64, 256>>>();
    k_dfe1<<<PTOT / 128, 256, SM1>>>(x, conv1_w, conv1_b);
    k_conv<<<dim3(16, 16, 2), 256, SM2>>>(conv2_w, conv2_b);
    k_dfe3<<<148, 512, SM3>>>(x, conv3_w, conv3_b, dfe_lw, dfe_lb);
    k_vp<<<(NWIN * 384 + 255) / 256, 256>>>(sl_w, sl_b);
    k_sp<<<NWIN * 6, 256>>>();
    k_ch<<<NWIN, 512, SMC>>>();
    k_proj<<<148, 512, SMP>>>(proj_w, proj_b, out);
}

// round 3
// speedup vs baseline: 1.6389x; 1.2418x over previous
#include <cuda_runtime.h>
#include <math.h>

// ---------------- problem constants ----------------
#define BATCH 2
#define HH 256
#define WW_ 256
#define CC 180
#define C5 36
#define NHD 6
#define HD 15
#define L 256
#define ML 64
#define NWIN 512
#define PTOT (BATCH*HH*WW_)

typedef unsigned long long u64;

__device__ __forceinline__ u64 f2pack(float lo, float hi) {
    u64 r; asm("mov.b64 %0, {%1,%2};" : "=l"(r) : "f"(lo), "f"(hi)); return r;
}
__device__ __forceinline__ void f2unpack(u64 v, float& a, float& b) {
    asm("mov.b64 {%0,%1}, %2;" : "=f"(a), "=f"(b) : "l"(v));
}
__device__ __forceinline__ u64 f2fma(u64 a, u64 b, u64 c) {
    u64 d; asm("fma.rn.f32x2 %0, %1, %2, %3;" : "=l"(d) : "l"(a), "l"(b), "l"(c)); return d;
}
__device__ __forceinline__ float f2hadd(u64 v) {
    float a, b; f2unpack(v, a, b); return a + b;
}

// ---------------- device scratch ----------------
__device__ float s_y1[PTOT * C5];
__device__ float s_y2[PTOT * C5];
__device__ float s_qv[PTOT * CC];
__device__ float s_cat[PTOT * CC];
__device__ float s_vp[NWIN * NHD * ML * HD];
__device__ float s_rpb[NHD * L * ML];
__device__ float s_tab[961 * NHD];

// ================= position-bias MLP table (961 x 6) =================
__global__ void k_postab(const float* __restrict__ pw, const float* __restrict__ pb,
                         const float* __restrict__ g1, const float* __restrict__ b1,
                         const float* __restrict__ m1w, const float* __restrict__ m1b,
                         const float* __restrict__ g2, const float* __restrict__ b2,
                         const float* __restrict__ m2w, const float* __restrict__ m2b,
                         const float* __restrict__ g3, const float* __restrict__ b3,
                         const float* __restrict__ m3w, const float* __restrict__ m3b) {
    int t = blockIdx.x * blockDim.x + threadIdx.x;
    if (t >= 961) return;
    int a = t / 31, bcol = t - a * 31;
    float gx = (float)a - 15.f, gy = (float)bcol - 15.f;
    float p[11], q[11];
#pragma unroll
    for (int j = 0; j < 11; j++) p[j] = gx * pw[j] + gy * pw[11 + j] + pb[j];
    {
        float m = 0.f;
#pragma unroll
        for (int j = 0; j < 11; j++) m += p[j];
        m *= (1.f / 11.f);
        float v = 0.f;
#pragma unroll
        for (int j = 0; j < 11; j++) { float d = p[j] - m; v += d * d; }
        v *= (1.f / 11.f);
        float inv = 1.f / sqrtf(v + 1e-5f);
#pragma unroll
        for (int j = 0; j < 11; j++) {
            float h = (p[j] - m) * inv * g1[j] + b1[j];
            q[j] = h > 0.f ? h : 0.f;
        }
#pragma unroll
        for (int j = 0; j < 11; j++) {
            float acc = m1b[j];
#pragma unroll
            for (int k = 0; k < 11; k++) acc += q[k] * m1w[k * 11 + j];
            p[j] = acc;
        }
    }
    {
        float m = 0.f;
#pragma unroll
        for (int j = 0; j < 11; j++) m += p[j];
        m *= (1.f / 11.f);
        float v = 0.f;
#pragma unroll
        for (int j = 0; j < 11; j++) { float d = p[j] - m; v += d * d; }
        v *= (1.f / 11.f);
        float inv = 1.f / sqrtf(v + 1e-5f);
#pragma unroll
        for (int j = 0; j < 11; j++) {
            float h = (p[j] - m) * inv * g2[j] + b2[j];
            q[j] = h > 0.f ? h : 0.f;
        }
#pragma unroll
        for (int j = 0; j < 11; j++) {
            float acc = m2b[j];
#pragma unroll
            for (int k = 0; k < 11; k++) acc += q[k] * m2w[k * 11 + j];
            p[j] = acc;
        }
    }
    {
        float m = 0.f;
#pragma unroll
        for (int j = 0; j < 11; j++) m += p[j];
        m *= (1.f / 11.f);
        float v = 0.f;
#pragma unroll
        for (int j = 0; j < 11; j++) { float d = p[j] - m; v += d * d; }
        v *= (1.f / 11.f);
        float inv = 1.f / sqrtf(v + 1e-5f);
#pragma unroll
        for (int j = 0; j < 11; j++) {
            float h = (p[j] - m) * inv * g3[j] + b3[j];
            q[j] = h > 0.f ? h : 0.f;
        }
#pragma unroll
        for (int n = 0; n < 6; n++) {
            float acc = m3b[n];
#pragma unroll
            for (int k = 0; k < 11; k++) acc += q[k] * m3w[k * 6 + n];
            s_tab[t * 6 + n] = acc;
        }
    }
}

// ================= rpb gather/average =================
__global__ void k_rpb() {
    int u = blockIdx.x * blockDim.x + threadIdx.x;
    int i = u >> 6, m = u & 63;
    int hi = i >> 4, wi = i & 15;
    int mh = m >> 3, mw = m & 7;
    float acc[6] = {0.f, 0.f, 0.f, 0.f, 0.f, 0.f};
#pragma unroll
    for (int rh = 0; rh < 2; rh++)
#pragma unroll
        for (int rw = 0; rw < 2; rw++) {
            int jh = mh * 2 + rh, jw = mw * 2 + rw;
            int idx = (hi - jh + 15) * 31 + (wi - jw + 15);
            const float* tr = s_tab + idx * 6;
#pragma unroll
            for (int n = 0; n < 6; n++) acc[n] += tr[n];
        }
#pragma unroll
    for (int n = 0; n < 6; n++) s_rpb[n * 16384 + u] = acc[n] * 0.25f;
}

// ================= DFE stage 1 (unchanged) =================
__global__ __launch_bounds__(256, 1) void k_dfe1(const float* __restrict__ x,
                                                 const float* __restrict__ w,
                                                 const float* __restrict__ b) {
    extern __shared__ float sm[];
    float* xs = sm;
    float* ws = sm + 128 * 180;
    int row0 = blockIdx.x * 128;
    int tid = threadIdx.x;
    {
        const float4* src = (const float4*)(x + row0 * 180);
        float4* dst = (float4*)xs;
        for (int t = tid; t < 128 * 45; t += 256) dst[t] = src[t];
    }
    for (int t = tid; t < 180 * 40; t += 256) {
        int k = t / 40, c = t - k * 40;
        ws[t] = (c < 36) ? w[k * 36 + c] : 0.f;
    }
    __syncthreads();
    int tr = tid >> 3, tc = tid & 7;
    int r0 = tr * 4, c0 = tc * 5;
    float acc[4][5];
#pragma unroll
    for (int i = 0; i < 4; i++)
#pragma unroll
        for (int j = 0; j < 5; j++) acc[i][j] = 0.f;
    for (int k = 0; k < 180; k++) {
        float av[4];
#pragma unroll
        for (int i = 0; i < 4; i++) av[i] = xs[(r0 + i) * 180 + k];
#pragma unroll
        for (int j = 0; j < 5; j++) {
            float bv = ws[k * 40 + c0 + j];
#pragma unroll
            for (int i = 0; i < 4; i++) acc[i][j] = fmaf(av[i], bv, acc[i][j]);
        }
    }
#pragma unroll
    for (int j = 0; j < 5; j++) {
        int c = c0 + j;
        if (c < 36) {
            float bc = b[c];
#pragma unroll
            for (int i = 0; i < 4; i++) {
                float v = acc[i][j] + bc;
                s_y1[(row0 + r0 + i) * 36 + c] = v > 0.f ? v : 0.2f * v;
            }
        }
    }
}

// ================= DFE stage 2: conv (unchanged) =================
__global__ __launch_bounds__(256, 2) void k_conv(const float* __restrict__ w,
                                                 const float* __restrict__ bias) {
    extern __shared__ float sm[];
    float* hs = sm;
    float* ws = sm + 18 * 18 * 37;
    int bImg = blockIdx.z, ty = blockIdx.y, tx = blockIdx.x;
    int tid = threadIdx.x;
    int y0 = ty * 16 - 1, x0 = tx * 16 - 1;
    for (int t = tid; t < 18 * 18 * 36; t += 256) {
        int pix = t / 36, ci = t - pix * 36;
        int py = pix / 18, px = pix - py * 18;
        int gy = y0 + py, gx = x0 + px;
        float v = 0.f;
        if (gy >= 0 && gy < 256 && gx >= 0 && gx < 256)
            v = s_y1[((bImg * 256 + gy) * 256 + gx) * 36 + ci];
        hs[pix * 37 + ci] = v;
    }
    for (int t = tid; t < 9 * 36 * 36; t += 256) ws[t] = w[t];
    __syncthreads();

    int pg = tid >> 2, cg = tid & 3;
    int ch0 = cg * 9;
    float acc[4][9];
#pragma unroll
    for (int i = 0; i < 4; i++)
#pragma unroll
        for (int j = 0; j < 9; j++) acc[i][j] = 0.f;
#pragma unroll
    for (int kh = 0; kh < 3; kh++)
#pragma unroll
        for (int kw = 0; kw < 3; kw++) {
            for (int ci = 0; ci < 36; ci++) {
                float vv[4];
#pragma unroll
                for (int ip = 0; ip < 4; ip++) {
                    int p = pg * 4 + ip;
                    int py = p >> 4, px = p & 15;
                    vv[ip] = hs[((py + kh) * 18 + px + kw) * 37 + ci];
                }
                const float* wr = ws + ((kh * 3 + kw) * 36 + ci) * 36 + ch0;
#pragma unroll
                for (int jc = 0; jc < 9; jc++) {
                    float wv = wr[jc];
#pragma unroll
                    for (int ip = 0; ip < 4; ip++) acc[ip][jc] = fmaf(vv[ip], wv, acc[ip][jc]);
                }
            }
        }
#pragma unroll
    for (int ip = 0; ip < 4; ip++) {
        int p = pg * 4 + ip;
        int py = p >> 4, px = p & 15;
        int gaddr = ((bImg * 256 + ty * 16 + py) * 256 + tx * 16 + px) * 36;
#pragma unroll
        for (int jc = 0; jc < 9; jc++) {
            int co = ch0 + jc;
            float v = acc[ip][jc] + bias[co];
            s_y2[gaddr + co] = v > 0.f ? v : 0.2f * v;
        }
    }
}

// ============ DFE stage 3 (PERSISTENT, f32x2) ============
// smem: w3t[192][19 f2], wlt[192][91 f2] (k-transposed), xs 64x180, y2s 64x36
__global__ __launch_bounds__(512, 1) void k_dfe3(const float* __restrict__ x,
                                                 const float* __restrict__ w3, const float* __restrict__ b3,
                                                 const float* __restrict__ wl, const float* __restrict__ bl) {
    extern __shared__ float sm[];
    float* w3t = sm;                  // 192*38 floats
    float* wlt = w3t + 192 * 38;      // 192*182 floats
    float* xs  = wlt + 192 * 182;     // 64*180
    float* y2s = xs + 64 * 180;       // 64*36
    int tid = threadIdx.x;
    for (int t = tid; t < 192 * 19; t += 512) {
        int c = t / 19, kp = t - c * 19;
        float a = 0.f, bb = 0.f;
        if (c < 180 && kp < 18) { a = w3[(2 * kp) * 180 + c]; bb = w3[(2 * kp + 1) * 180 + c]; }
        w3t[2 * t] = a; w3t[2 * t + 1] = bb;
    }
    for (int t = tid; t < 192 * 91; t += 512) {
        int c = t / 91, kp = t - c * 91;
        float a = 0.f, bb = 0.f;
        if (c < 180 && kp < 90) { a = wl[(2 * kp) * 180 + c]; bb = wl[(2 * kp + 1) * 180 + c]; }
        wlt[2 * t] = a; wlt[2 * t + 1] = bb;
    }
    int warp = tid >> 5, lane = tid & 31;
    int r0 = warp * 4;
    int cidx[6]; float bcr[6], dcr[6];
#pragma unroll
    for (int j = 0; j < 6; j++) {
        int c = lane + 32 * j; cidx[j] = c;
        bcr[j] = (c < 180) ? b3[c] : 0.f;
        dcr[j] = (c < 180) ? bl[c] : 0.f;
    }

    for (int tile = blockIdx.x; tile < PTOT / 64; tile += gridDim.x) {
        int row0 = tile * 64;
        __syncthreads();
        {
            const float4* src = (const float4*)(x + row0 * 180);
            float4* dst = (float4*)xs;
            for (int t = tid; t < 64 * 45; t += 512) dst[t] = src[t];
            const float4* ys = (const float4*)(s_y2 + row0 * 36);
            float4* yd = (float4*)y2s;
            for (int t = tid; t < 64 * 9; t += 512) yd[t] = ys[t];
        }
        __syncthreads();

        // part A: y2 @ w3  (K=36 -> 18 pairs)
        u64 accA[4][6];
#pragma unroll
        for (int i = 0; i < 4; i++)
#pragma unroll
            for (int j = 0; j < 6; j++) accA[i][j] = 0ull;
        for (int kp = 0; kp < 18; kp++) {
            u64 av[4], bv[6];
#pragma unroll
            for (int i = 0; i < 4; i++) av[i] = *(const u64*)(y2s + (r0 + i) * 36 + 2 * kp);
#pragma unroll
            for (int j = 0; j < 6; j++) bv[j] = *(const u64*)(w3t + cidx[j] * 38 + 2 * kp);
#pragma unroll
            for (int i = 0; i < 4; i++)
#pragma unroll
                for (int j = 0; j < 6; j++) accA[i][j] = f2fma(av[i], bv[j], accA[i][j]);
        }
        float aA[4][6];
#pragma unroll
        for (int i = 0; i < 4; i++)
#pragma unroll
            for (int j = 0; j < 6; j++) aA[i][j] = f2hadd(accA[i][j]) + bcr[j];

        // part D: x @ wl  (K=180 -> 90 pairs)
        u64 accD[4][6];
#pragma unroll
        for (int i = 0; i < 4; i++)
#pragma unroll
            for (int j = 0; j < 6; j++) accD[i][j] = 0ull;
        for (int kp = 0; kp < 90; kp++) {
            u64 av[4], bv[6];
#pragma unroll
            for (int i = 0; i < 4; i++) av[i] = *(const u64*)(xs + (r0 + i) * 180 + 2 * kp);
#pragma unroll
            for (int j = 0; j < 6; j++) bv[j] = *(const u64*)(wlt + cidx[j] * 182 + 2 * kp);
#pragma unroll
            for (int i = 0; i < 4; i++)
#pragma unroll
                for (int j = 0; j < 6; j++) accD[i][j] = f2fma(av[i], bv[j], accD[i][j]);
        }
#pragma unroll
        for (int j = 0; j < 6; j++) {
            int c = cidx[j];
            if (c < 180) {
#pragma unroll
                for (int i = 0; i < 4; i++)
                    s_qv[(row0 + r0 + i) * 180 + c] = aA[i][j] * (f2hadd(accD[i][j]) + dcr[j]);
            }
        }
    }
}

// ================= vp (unchanged) =================
__global__ void k_vp(const float* __restrict__ sl_w, const float* __restrict__ sl_b) {
    int u = blockIdx.x * blockDim.x + threadIdx.x;
    if (u >= NWIN * 384) return;
    int w = u / 384;
    int rem = u - w * 384;
    int n = rem >> 6, m = rem & 63;
    int b = w >> 8, wh = (w >> 4) & 15, ww = w & 15;
    int mh = m >> 3, mw = m & 7;
    int gh = wh * 16 + mh * 2, gw = ww * 16 + mw * 2;
    const float* q00 = s_qv + ((b * 256 + gh) * 256 + gw) * 180 + 90 + n * 15;
    const float* q01 = q00 + 180;
    const float* q10 = q00 + 256 * 180;
    const float* q11 = q10 + 180;
    float w0 = sl_w[0], w1 = sl_w[1], w2 = sl_w[2], w3 = sl_w[3], bb = sl_b[0];
    float* out = s_vp + ((w * 6 + n) * 64 + m) * 15;
#pragma unroll
    for (int c = 0; c < 15; c++)
        out[c] = bb + q00[c] * w0 + q01[c] * w1 + q10[c] * w2 + q11[c] * w3;
}

// ================= spatial correlation (f32x2) =================
__global__ __launch_bounds__(256, 3) void k_sp() {
    __shared__ float vps[64 * 16];
    int blk = blockIdx.x;
    int w = blk / 6, n = blk - w * 6;
    int b = w >> 8, wh = (w >> 4) & 15, ww = w & 15;
    int tid = threadIdx.x;
    const float* vsrc = s_vp + (w * 6 + n) * 960;
    for (int t = tid; t < 960; t += 256) {
        int m = t / 15, c = t - m * 15;
        vps[m * 16 + c] = vsrc[t];
    }
    if (tid < 64) vps[tid * 16 + 15] = 0.f;
    __syncthreads();

    int l = tid;
    int gh = wh * 16 + (l >> 4), gw = ww * 16 + (l & 15);
    int gpix = ((b * 256 + gh) * 256 + gw) * 180;
    float qr[15];
#pragma unroll
    for (int c = 0; c < 15; c++) qr[c] = s_qv[gpix + n * 15 + c];
    u64 qr2[8];
#pragma unroll
    for (int cp = 0; cp < 7; cp++) qr2[cp] = f2pack(qr[2 * cp], qr[2 * cp + 1]);
    qr2[7] = f2pack(qr[14], 0.f);

    u64 out2[8];
#pragma unroll
    for (int cp = 0; cp < 8; cp++) out2[cp] = 0ull;
    const float* rp = s_rpb + n * 16384 + l * 64;

#pragma unroll
    for (int ch = 0; ch < 4; ch++) {
        float co[16];
#pragma unroll
        for (int mm = 0; mm < 16; mm++) {
            int m = ch * 16 + mm;
            u64 a = 0ull;
#pragma unroll
            for (int cp = 0; cp < 8; cp++)
                a = f2fma(qr2[cp], *(const u64*)(vps + m * 16 + 2 * cp), a);
            co[mm] = f2hadd(a) * (1.0f / 15.0f) + rp[m];
        }
#pragma unroll
        for (int mm = 0; mm < 16; mm++) {
            int m = ch * 16 + mm;
            u64 c2 = f2pack(co[mm], co[mm]);
#pragma unroll
            for (int cp = 0; cp < 8; cp++)
                out2[cp] = f2fma(c2, *(const u64*)(vps + m * 16 + 2 * cp), out2[cp]);
        }
    }
    float o[16];
#pragma unroll
    for (int cp = 0; cp < 8; cp++) f2unpack(out2[cp], o[2 * cp], o[2 * cp + 1]);
#pragma unroll
    for (int c = 0; c < 15; c++) s_cat[gpix + n * 15 + c] = o[c];
}

// ================= channel correlation (f32x2, channel-major transpose) =================
#define QP 258  // floats per channel row (129 float2, odd f2-stride => conflict-free)
__global__ __launch_bounds__(512, 1) void k_ch() {
    extern __shared__ float sm[];
    float* q = sm;               // 186 * 258 floats (rows 180..185 zeroed)
    float* ccs = sm + 186 * QP;  // 90*90
    int w = blockIdx.x;
    int b = w >> 8, wh = (w >> 4) & 15, ww = w & 15;
    int tid = threadIdx.x;

    for (int t = tid; t < 6 * QP; t += 512) q[180 * QP + t] = 0.f;
    for (int t = tid; t < 256 * 45; t += 512) {
        int l = t / 45, j = t - l * 45;
        int gh = wh * 16 + (l >> 4), gw = ww * 16 + (l & 15);
        float4 v = *(const float4*)(s_qv + ((b * 256 + gh) * 256 + gw) * 180 + j * 4);
        int c = 4 * j;
        q[(c    ) * QP + l] = v.x;
        q[(c + 1) * QP + l] = v.y;
        q[(c + 2) * QP + l] = v.z;
        q[(c + 3) * QP + l] = v.w;
    }
    __syncthreads();

    // phase 1: cc[c][d] = (1/256) sum_l qc[l][c] vc[l][d]  (pair over l)
    {
        int wc = tid >> 5, td = tid & 31;
        u64 acc[6][3];
#pragma unroll
        for (int i = 0; i < 6; i++)
#pragma unroll
            for (int j = 0; j < 3; j++) acc[i][j] = 0ull;
        for (int lp = 0; lp < 128; lp++) {
            u64 qa[6], vb[3];
#pragma unroll
            for (int i = 0; i < 6; i++) qa[i] = *(const u64*)(q + (wc + 16 * i) * QP + 2 * lp);
#pragma unroll
            for (int j = 0; j < 3; j++) vb[j] = *(const u64*)(q + (90 + td + 32 * j) * QP + 2 * lp);
#pragma unroll
            for (int i = 0; i < 6; i++)
#pragma unroll
                for (int j = 0; j < 3; j++) acc[i][j] = f2fma(qa[i], vb[j], acc[i][j]);
        }
#pragma unroll
        for (int i = 0; i < 6; i++)
#pragma unroll
            for (int j = 0; j < 3; j++) {
                int c = wc + 16 * i, d = td + 32 * j;
                if (c < 90 && d < 90) ccs[c * 90 + d] = f2hadd(acc[i][j]) * (1.f / 256.f);
            }
    }
    __syncthreads();

    // phase 2: x_ch[l][c] = sum_d cc[c][d] vc[l][d]  (l-pairs packed)
    {
        int tl = tid & 31, wc = tid >> 5;
        int ci[6];
#pragma unroll
        for (int jc = 0; jc < 6; jc++) {
            int c = wc + 16 * jc;
            ci[jc] = (c < 90) ? c : 89;
        }
        u64 acc[4][6];
#pragma unroll
        for (int il = 0; il < 4; il++)
#pragma unroll
            for (int jc = 0; jc < 6; jc++) acc[il][jc] = 0ull;
        for (int d = 0; d < 90; d++) {
            u64 vv[4];
#pragma unroll
            for (int il = 0; il < 4; il++)
                vv[il] = *(const u64*)(q + (90 + d) * QP + 2 * (tl + 32 * il));
#pragma unroll
            for (int jc = 0; jc < 6; jc++) {
                float cv = ccs[ci[jc] * 90 + d];
                u64 cvp = f2pack(cv, cv);
#pragma unroll
                for (int il = 0; il < 4; il++) acc[il][jc] = f2fma(vv[il], cvp, acc[il][jc]);
            }
        }
#pragma unroll
        for (int jc = 0; jc < 6; jc++) {
            int c = wc + 16 * jc;
            if (c < 90) {
#pragma unroll
                for (int il = 0; il < 4; il++) {
                    int l0 = 2 * (tl + 32 * il);
                    float a0, a1;
                    f2unpack(acc[il][jc], a0, a1);
                    int gh0 = wh * 16 + (l0 >> 4), gw0 = ww * 16 + (l0 & 15);
                    s_cat[((b * 256 + gh0) * 256 + gw0) * 180 + 90 + c] = a0;
                    int l1 = l0 + 1;
                    int gh1 = wh * 16 + (l1 >> 4), gw1 = ww * 16 + (l1 & 15);
                    s_cat[((b * 256 + gh1) * 256 + gw1) * 180 + 90 + c] = a1;
                }
            }
        }
    }
}

// ============ final projection (PERSISTENT, f32x2) ============
__global__ __launch_bounds__(512, 1) void k_proj(const float* __restrict__ wp,
                                                 const float* __restrict__ bp,
                                                 float* __restrict__ out) {
    extern __shared__ float sm[];
    float* wpt = sm;                  // 192*182 floats
    float* xs = wpt + 192 * 182;      // 64*180
    int tid = threadIdx.x;
    for (int t = tid; t < 192 * 91; t += 512) {
        int c = t / 91, kp = t - c * 91;
        float a = 0.f, bb = 0.f;
        if (c < 180 && kp < 90) { a = wp[(2 * kp) * 180 + c]; bb = wp[(2 * kp + 1) * 180 + c]; }
        wpt[2 * t] = a; wpt[2 * t + 1] = bb;
    }
    int warp = tid >> 5, lane = tid & 31;
    int r0 = warp * 4;
    int cidx[6]; float bcr[6];
#pragma unroll
    for (int j = 0; j < 6; j++) {
        int c = lane + 32 * j; cidx[j] = c;
        bcr[j] = (c < 180) ? bp[c] : 0.f;
    }

    for (int tile = blockIdx.x; tile < PTOT / 64; tile += gridDim.x) {
        int row0 = tile * 64;
        __syncthreads();
        {
            const float4* src = (const float4*)(s_cat + row0 * 180);
            float4* dst = (float4*)xs;
            for (int t = tid; t < 64 * 45; t += 512) dst[t] = src[t];
        }
        __syncthreads();

        u64 acc[4][6];
#pragma unroll
        for (int i = 0; i < 4; i++)
#pragma unroll
            for (int j = 0; j < 6; j++) acc[i][j] = 0ull;
        for (int kp = 0; kp < 90; kp++) {
            u64 av[4], bv[6];
#pragma unroll
            for (int i = 0; i < 4; i++) av[i] = *(const u64*)(xs + (r0 + i) * 180 + 2 * kp);
#pragma unroll
            for (int j = 0; j < 6; j++) bv[j] = *(const u64*)(wpt + cidx[j] * 182 + 2 * kp);
#pragma unroll
            for (int i = 0; i < 4; i++)
#pragma unroll
                for (int j = 0; j < 6; j++) acc[i][j] = f2fma(av[i], bv[j], acc[i][j]);
        }
#pragma unroll
        for (int j = 0; j < 6; j++) {
            int c = cidx[j];
            if (c < 180) {
#pragma unroll
                for (int i = 0; i < 4; i++)
                    out[(row0 + r0 + i) * 180 + c] = f2hadd(acc[i][j]) + bcr[j];
            }
        }
    }
}

// ================= launch =================
extern "C" void kernel_launch(void* const* d_in, const int* in_sizes, int n_in,
                              void* d_out, int out_size) {
    const float* x        = (const float*)d_in[0];
    const float* conv1_w  = (const float*)d_in[1];
    const float* conv1_b  = (const float*)d_in[2];
    const float* conv2_w  = (const float*)d_in[3];
    const float* conv2_b  = (const float*)d_in[4];
    const float* conv3_w  = (const float*)d_in[5];
    const float* conv3_b  = (const float*)d_in[6];
    const float* dfe_lw   = (const float*)d_in[7];
    const float* dfe_lb   = (const float*)d_in[8];
    const float* sl_w     = (const float*)d_in[9];
    const float* sl_b     = (const float*)d_in[10];
    const float* pos_w    = (const float*)d_in[11];
    const float* pos_b    = (const float*)d_in[12];
    const float* ln1_g    = (const float*)d_in[13];
    const float* ln1_b    = (const float*)d_in[14];
    const float* mlp1_w   = (const float*)d_in[15];
    const float* mlp1_b   = (const float*)d_in[16];
    const float* ln2_g    = (const float*)d_in[17];
    const float* ln2_b    = (const float*)d_in[18];
    const float* mlp2_w   = (const float*)d_in[19];
    const float* mlp2_b   = (const float*)d_in[20];
    const float* ln3_g    = (const float*)d_in[21];
    const float* ln3_b    = (const float*)d_in[22];
    const float* mlp3_w   = (const float*)d_in[23];
    const float* mlp3_b   = (const float*)d_in[24];
    const float* proj_w   = (const float*)d_in[25];
    const float* proj_b   = (const float*)d_in[26];
    float* out = (float*)d_out;

    const int SM1 = (128 * 180 + 180 * 40) * 4;
    const int SM2 = (18 * 18 * 37 + 9 * 36 * 36) * 4;
    const int SM3 = (192 * 38 + 192 * 182 + 64 * 180 + 64 * 36) * 4;
    const int SMC = (186 * QP + 90 * 90) * 4;
    const int SMP = (192 * 182 + 64 * 180) * 4;

    cudaFuncSetAttribute(k_dfe1, cudaFuncAttributeMaxDynamicSharedMemorySize, SM1);
    cudaFuncSetAttribute(k_conv, cudaFuncAttributeMaxDynamicSharedMemorySize, SM2);
    cudaFuncSetAttribute(k_dfe3, cudaFuncAttributeMaxDynamicSharedMemorySize, SM3);
    cudaFuncSetAttribute(k_ch,   cudaFuncAttributeMaxDynamicSharedMemorySize, SMC);
    cudaFuncSetAttribute(k_proj, cudaFuncAttributeMaxDynamicSharedMemorySize, SMP);

    k_postab<<<4, 256>>>(pos_w, pos_b, ln1_g, ln1_b, mlp1_w, mlp1_b,
                         ln2_g, ln2_b, mlp2_w, mlp2_b, ln3_g, ln3_b, mlp3_w, mlp3_b);
    k_rpb<<<64, 256>>>();
    k_dfe1<<<PTOT / 128, 256, SM1>>>(x, conv1_w, conv1_b);
    k_conv<<<dim3(16, 16, 2), 256, SM2>>>(conv2_w, conv2_b);
    k_dfe3<<<148, 512, SM3>>>(x, conv3_w, conv3_b, dfe_lw, dfe_lb);
    k_vp<<<(NWIN * 384 + 255) / 256, 256>>>(sl_w, sl_b);
    k_sp<<<NWIN * 6, 256>>>();
    k_ch<<<NWIN, 512, SMC>>>();
    k_proj<<<148, 512, SMP>>>(proj_w, proj_b, out);
}